// round 16
// baseline (speedup 1.0000x reference)
#include <cuda_runtime.h>
#include <cuda_fp16.h>
#include <cstdint>

// ============================================================================
// OutlierAwareLinear: y = x @ W^T + b, then per-token outlier-aware fake quant.
// GEMM: 3-term FP16 split (hi/lo) on mma.sync.m16n8k16.f16.f32:
//   a*b ~= ah*bh + ah*bl + al*bh  (al*bl ~2^-22 dropped; fp32-like accuracy)
// x,W pre-split once into fp16 hi/lo; GEMM streams via cp.async.
// THIS ROUND: 512 threads / 16 warps -> 4 warps per SMSP (was 2). Warp tile
// 32x64, acc = 64 regs/thread (fits the 128-reg cap at 512 thr). All prior
// bubble sources (ldsm shadow, HMMA RAW, fill) are intra-warp dependencies;
// doubling resident warps per scheduler covers them. Targets the stable
// ~80% tensor / 15.5% issue ceiling of every 256-thread variant.
// ============================================================================

#define M_DIM 16384
#define K_DIM 2048
#define N_DIM 2048
#define BM 128
#define BN 256
#define BK 64                    // 64 fp16 = 128 bytes per row
#define NCHUNKS (K_DIM / BK)     // 32
#define NTHREADS 512

// smem per buffer: Ahi 16K | Alo 16K | Bhi 32K | Blo 32K = 96KB; 2 buffers
#define OFF_AHI 0
#define OFF_ALO 16384
#define OFF_BHI 32768
#define OFF_BLO 65536
#define BUF_STRIDE 98304
#define SMEM_TOTAL (2 * BUF_STRIDE)   // 192 KB

// ---- global fp16 hi/lo scratch (static __device__; no runtime alloc) ----
__device__ __half g_Ahi[(size_t)M_DIM * K_DIM];   // 64 MB
__device__ __half g_Alo[(size_t)M_DIM * K_DIM];   // 64 MB
__device__ __half g_Whi[(size_t)N_DIM * K_DIM];   // 8 MB
__device__ __half g_Wlo[(size_t)N_DIM * K_DIM];   // 8 MB

__device__ __forceinline__ uint32_t smem_u32(const void* p) {
    return (uint32_t)__cvta_generic_to_shared(p);
}
__device__ __forceinline__ uint32_t swz(uint32_t off) {
    return off ^ ((off >> 3) & 0x70);
}
__device__ __forceinline__ void ldsm_x4(uint32_t r[4], uint32_t addr) {
    asm volatile("ldmatrix.sync.aligned.m8n8.x4.shared.b16 {%0,%1,%2,%3}, [%4];"
                 : "=r"(r[0]), "=r"(r[1]), "=r"(r[2]), "=r"(r[3]) : "r"(addr));
}
__device__ __forceinline__ void mma_f16(float c[4], const uint32_t a[4],
                                        const uint32_t* b) {
    asm volatile(
        "mma.sync.aligned.m16n8k16.row.col.f32.f16.f16.f32 "
        "{%0,%1,%2,%3}, {%4,%5,%6,%7}, {%8,%9}, {%0,%1,%2,%3};"
        : "+f"(c[0]), "+f"(c[1]), "+f"(c[2]), "+f"(c[3])
        : "r"(a[0]), "r"(a[1]), "r"(a[2]), "r"(a[3]), "r"(b[0]), "r"(b[1]));
}
__device__ __forceinline__ void cp16(uint32_t dst, const void* src) {
    asm volatile("cp.async.cg.shared.global [%0], [%1], 16;" :: "r"(dst), "l"(src));
}
#define CP_COMMIT() asm volatile("cp.async.commit_group;" ::: "memory")
#define CP_WAIT1()  asm volatile("cp.async.wait_group 1;" ::: "memory")

// ---------------------------------------------------------------------------
// Split kernel: x and W -> fp16 (hi, lo). One float4 per thread.
// ---------------------------------------------------------------------------
#define NX4 ((size_t)M_DIM * K_DIM / 4)
#define NW4 ((size_t)N_DIM * K_DIM / 4)

__global__ __launch_bounds__(256)
void oal_split_kernel(const float4* __restrict__ x4, const float4* __restrict__ w4) {
    const size_t i = (size_t)blockIdx.x * blockDim.x + threadIdx.x;
    float4 v;
    __half2 *hi, *lo;
    size_t o;
    if (i < NX4) {
        v = x4[i];
        hi = (__half2*)g_Ahi; lo = (__half2*)g_Alo; o = i * 2;
    } else if (i < NX4 + NW4) {
        v = w4[i - NX4];
        hi = (__half2*)g_Whi; lo = (__half2*)g_Wlo; o = (i - NX4) * 2;
    } else return;

    __half2 h0 = __floats2half2_rn(v.x, v.y);
    __half2 h1 = __floats2half2_rn(v.z, v.w);
    float2 f0 = __half22float2(h0);
    float2 f1 = __half22float2(h1);
    hi[o]     = h0;
    hi[o + 1] = h1;
    lo[o]     = __floats2half2_rn(v.x - f0.x, v.y - f0.y);
    lo[o + 1] = __floats2half2_rn(v.z - f1.x, v.w - f1.y);
}

// ---------------------------------------------------------------------------
// GEMM: CTA 128x256, 16 warps (4M x 4N), warp tile 32x64, fp16 hi/lo 3-term.
// ---------------------------------------------------------------------------
__global__ __launch_bounds__(NTHREADS, 1)
void oal_gemm_f16(const float* __restrict__ bias, float* __restrict__ Y) {
    extern __shared__ char smem[];
    const uint32_t sb = smem_u32(smem);

    const int tid = threadIdx.x;
    const int lane = tid & 31;
    const int wid = tid >> 5;                  // 0..15
    const int warp_m = (wid & 3) * 32;
    const int warp_n = (wid >> 2) * 64;
    const int block_m = blockIdx.y * BM;
    const int block_n = blockIdx.x * BN;

    // ldmatrix lane offsets (unswizzled; swizzle via XOR at use — proven)
    const uint32_t swmask = (lane & 7) << 4;
    uint32_t a_off[2];
#pragma unroll
    for (int mt = 0; mt < 2; mt++) {
        uint32_t row = warp_m + mt * 16 + (lane & 15);
        a_off[mt] = row * 128 + (lane >> 4) * 16;
    }
    uint32_t b_off[4];
#pragma unroll
    for (int ntp = 0; ntp < 4; ntp++) {
        uint32_t n = warp_n + ntp * 16 + ((lane >> 4) & 1) * 8 + (lane & 7);
        b_off[ntp] = n * 128 + ((lane >> 3) & 1) * 16;
    }

    // producer mapping: 512 threads, each owns 16B seg (tid&7) of rows
    // {rowg + 64p}; A: 2 rows, B: 4 rows -> 12 cp.async of 16B per thread.
    const int seg = tid & 7;
    const int rowg = tid >> 3;                 // 0..63
    const int c16 = seg * 16;
    const int kseg8 = seg * 8;

    const __half* Ahi = g_Ahi + (size_t)(block_m + rowg) * K_DIM + kseg8;
    const __half* Alo = g_Alo + (size_t)(block_m + rowg) * K_DIM + kseg8;
    const __half* Bhi = g_Whi + (size_t)(block_n + rowg) * K_DIM + kseg8;
    const __half* Blo = g_Wlo + (size_t)(block_n + rowg) * K_DIM + kseg8;

    float acc[2][8][4];
#pragma unroll
    for (int mt = 0; mt < 2; mt++)
#pragma unroll
        for (int nt = 0; nt < 8; nt++)
#pragma unroll
            for (int j = 0; j < 4; j++) acc[mt][nt][j] = 0.0f;

    auto fill = [&](int c, int b) {
        const uint32_t base = sb + b * BUF_STRIDE;
        const int k0 = c * BK;
#pragma unroll
        for (int p = 0; p < 2; p++) {
            const uint32_t sw = swz((rowg + p * 64) * 128 + c16);
            cp16(base + OFF_AHI + sw, Ahi + (size_t)(p * 64) * K_DIM + k0);
            cp16(base + OFF_ALO + sw, Alo + (size_t)(p * 64) * K_DIM + k0);
        }
#pragma unroll
        for (int p = 0; p < 4; p++) {
            const uint32_t sw = swz((rowg + p * 64) * 128 + c16);
            cp16(base + OFF_BHI + sw, Bhi + (size_t)(p * 64) * K_DIM + k0);
            cp16(base + OFF_BLO + sw, Blo + (size_t)(p * 64) * K_DIM + k0);
        }
    };

    fill(0, 0); CP_COMMIT();
    fill(1, 1); CP_COMMIT();

    for (int c = 0; c < NCHUNKS; c++) {
        const int b = c & 1;
        const uint32_t cur = sb + b * BUF_STRIDE;

        CP_WAIT1();
        __syncthreads();

#pragma unroll
        for (int ks = 0; ks < 4; ks++) {
            uint32_t ah[2][4], al[2][4];
#pragma unroll
            for (int mt = 0; mt < 2; mt++) {
                const uint32_t ao = (a_off[mt] + ks * 32) ^ swmask;
                ldsm_x4(ah[mt], cur + OFF_AHI + ao);
                ldsm_x4(al[mt], cur + OFF_ALO + ao);
            }
#pragma unroll
            for (int ntp = 0; ntp < 4; ntp++) {
                const uint32_t bo = (b_off[ntp] + ks * 32) ^ swmask;
                uint32_t bh[4], bl[4];
                ldsm_x4(bh, cur + OFF_BHI + bo);
                ldsm_x4(bl, cur + OFF_BLO + bo);
                // term-major issue; per-quad order hh, hl, lh per k-step
                // (bit-identical to all fp16-split rounds)
#pragma unroll
                for (int t = 0; t < 2; t++)
#pragma unroll
                    for (int mt = 0; mt < 2; mt++)
                        mma_f16(acc[mt][2 * ntp + t], ah[mt], bh + 2 * t);  // hi*hi
#pragma unroll
                for (int t = 0; t < 2; t++)
#pragma unroll
                    for (int mt = 0; mt < 2; mt++)
                        mma_f16(acc[mt][2 * ntp + t], ah[mt], bl + 2 * t);  // hi*lo
#pragma unroll
                for (int t = 0; t < 2; t++)
#pragma unroll
                    for (int mt = 0; mt < 2; mt++)
                        mma_f16(acc[mt][2 * ntp + t], al[mt], bh + 2 * t);  // lo*hi
            }
        }

        __syncthreads();
        if (c + 2 < NCHUNKS) fill(c + 2, b);
        CP_COMMIT();
    }

    // ---- epilogue: acc -> gmem with bias ----
    const int g = lane >> 2;
    const int t4 = lane & 3;
#pragma unroll
    for (int mt = 0; mt < 2; mt++) {
        const int m0 = block_m + warp_m + mt * 16 + g;
#pragma unroll
        for (int nt = 0; nt < 8; nt++) {
            const int n0 = block_n + warp_n + nt * 8 + t4 * 2;
            const float2 bb = *(const float2*)(bias + n0);
            float2 v0, v1;
            v0.x = acc[mt][nt][0] + bb.x;
            v0.y = acc[mt][nt][1] + bb.y;
            v1.x = acc[mt][nt][2] + bb.x;
            v1.y = acc[mt][nt][3] + bb.y;
            *(float2*)(Y + (size_t)m0 * N_DIM + n0) = v0;
            *(float2*)(Y + (size_t)(m0 + 8) * N_DIM + n0) = v1;
        }
    }
}

// ---------------------------------------------------------------------------
// Per-token outlier-aware fake quant (66% of HBM peak).
// ---------------------------------------------------------------------------
#define QMAX 127.0f
#define OUTLIER_T 3.0f
#define Q_EPS 1e-6f

__global__ __launch_bounds__(256)
void oal_quant_kernel(float* __restrict__ Y) {
    const size_t row = blockIdx.x;
    float4* y4 = reinterpret_cast<float4*>(Y + row * (size_t)N_DIM);

    const int tid = threadIdx.x;
    float4 p = y4[tid];
    float4 q = y4[tid + 256];
    float v[8] = {p.x, p.y, p.z, p.w, q.x, q.y, q.z, q.w};

    float s = 0.0f, ss = 0.0f, amax = 0.0f;
#pragma unroll
    for (int i = 0; i < 8; i++) {
        s += v[i];
        ss = fmaf(v[i], v[i], ss);
        amax = fmaxf(amax, fabsf(v[i]));
    }
#pragma unroll
    for (int off = 16; off > 0; off >>= 1) {
        s += __shfl_xor_sync(0xFFFFFFFFu, s, off);
        ss += __shfl_xor_sync(0xFFFFFFFFu, ss, off);
        amax = fmaxf(amax, __shfl_xor_sync(0xFFFFFFFFu, amax, off));
    }

    __shared__ float red_s[8], red_ss[8], red_m[8];
    const int wid = tid >> 5;
    const int lid = tid & 31;
    if (lid == 0) { red_s[wid] = s; red_ss[wid] = ss; red_m[wid] = amax; }
    __syncthreads();

    if (wid == 0) {
        float s2 = (lid < 8) ? red_s[lid] : 0.0f;
        float ss2 = (lid < 8) ? red_ss[lid] : 0.0f;
        float m2 = (lid < 8) ? red_m[lid] : 0.0f;
#pragma unroll
        for (int off = 4; off > 0; off >>= 1) {
            s2 += __shfl_xor_sync(0xFFFFFFFFu, s2, off);
            ss2 += __shfl_xor_sync(0xFFFFFFFFu, ss2, off);
            m2 = fmaxf(m2, __shfl_xor_sync(0xFFFFFFFFu, m2, off));
        }
        if (lid == 0) { red_s[0] = s2; red_ss[0] = ss2; red_m[0] = m2; }
    }
    __syncthreads();

    const float inv_d = 1.0f / (float)N_DIM;
    const float mean = red_s[0] * inv_d;
    const float var = fmaxf(red_ss[0] * inv_d - mean * mean, 0.0f);
    const float thr = OUTLIER_T * sqrtf(var);
    const float scale = fmaxf(fminf(red_m[0], thr) / QMAX, Q_EPS);
    const float inv_scale = 1.0f / scale;

#pragma unroll
    for (int i = 0; i < 8; i++) {
        float x = v[i];
        float cl = fminf(fmaxf(x, -thr), thr);
        float fq = rintf(cl * inv_scale) * scale;
        v[i] = (fabsf(x) > thr) ? x : fq;
    }

    p.x = v[0]; p.y = v[1]; p.z = v[2]; p.w = v[3];
    q.x = v[4]; q.y = v[5]; q.z = v[6]; q.w = v[7];
    y4[tid] = p;
    y4[tid + 256] = q;
}

// Padding: captured ncu slot is our 4th launch; 2 nops put the GEMM there.
__global__ void oal_nop_kernel() {}

// ---------------------------------------------------------------------------

extern "C" void kernel_launch(void* const* d_in, const int* in_sizes, int n_in,
                              void* d_out, int out_size) {
    const float* x = (const float*)d_in[0];
    const float* W = (const float*)d_in[1];
    const float* b = (const float*)d_in[2];
    float* out = (float*)d_out;

    cudaFuncSetAttribute(oal_gemm_f16, cudaFuncAttributeMaxDynamicSharedMemorySize, SMEM_TOTAL);

    // 1) split x and W into fp16 hi/lo (~45us)
    const size_t total4 = NX4 + NW4;
    const int sblocks = (int)((total4 + 255) / 256);
    oal_split_kernel<<<sblocks, 256>>>((const float4*)x, (const float4*)W);

    // 2-3) nops so the GEMM lands in the ncu capture slot (launch #4)
    oal_nop_kernel<<<1, 32>>>();
    oal_nop_kernel<<<1, 32>>>();

    // 4) GEMM: 512 threads, 16 warps, 4 warps/SMSP
    dim3 ggrid(N_DIM / BN, M_DIM / BM);   // (8, 128)
    oal_gemm_f16<<<ggrid, NTHREADS, SMEM_TOTAL>>>(b, out);

    // 5) per-token quant
    oal_quant_kernel<<<M_DIM, 256>>>(out);
}